// round 10
// baseline (speedup 1.0000x reference)
#include <cuda_runtime.h>
#include <cstdint>

#define BB   1024
#define NJT  16
#define NBLK 128              // 8 i-tiles x 16 j-tiles of 128x128, one wave
#define RS   144              // int8 row: 128 B data + 16 B pad
#define QS   24.0f            // quantization scale
#define INV2S2 (2.0f / (QS * QS))

// byte offsets in dynamic SMEM
#define S_A   0               // 128 rows x 144
#define S_B   18432           // 128 rows x 144
#define S_NI  36864           // 256 floats (norms: [0:128)=A, [128:256)=B)
#define S_NP  37888           // 256 x 9 floats (partials); RED aliases
#define S_RED S_NP            // 4 x 128 floats (NP dead by then)
#define S_TOT 47104

__device__ float g_partial[NJT * BB];
__device__ float g_ppos[BB];
__device__ int   g_counter = 0;

__device__ __forceinline__ float frcp(float x) {
    float r;
    asm("rcp.approx.f32 %0, %1;" : "=f"(r) : "f"(x));
    return r;
}
__device__ __forceinline__ void ldsm4(uint32_t r[4], uint32_t p) {
    asm volatile("ldmatrix.sync.aligned.m8n8.x4.shared.b16 {%0,%1,%2,%3}, [%4];"
                 : "=r"(r[0]), "=r"(r[1]), "=r"(r[2]), "=r"(r[3]) : "r"(p));
}
__device__ __forceinline__ void mma_s8(int c[4], const uint32_t a[4],
                                       uint32_t b0, uint32_t b1) {
    asm volatile(
        "mma.sync.aligned.m16n8k32.row.col.s32.s8.s8.s32 "
        "{%0,%1,%2,%3}, {%4,%5,%6,%7}, {%8,%9}, {%0,%1,%2,%3};"
        : "+r"(c[0]), "+r"(c[1]), "+r"(c[2]), "+r"(c[3])
        : "r"(a[0]), "r"(a[1]), "r"(a[2]), "r"(a[3]), "r"(b0), "r"(b1));
}
// quantize float4 -> 4 packed s8 (k-order: x in byte0 .. w in byte3)
__device__ __forceinline__ uint32_t quant4(float4 v) {
    int x0 = __float2int_rn(v.x * QS), x1 = __float2int_rn(v.y * QS);
    int x2 = __float2int_rn(v.z * QS), x3 = __float2int_rn(v.w * QS);
    uint32_t t, d;
    asm("cvt.pack.sat.s8.s32.b32 %0, %1, %2, 0;" : "=r"(t) : "r"(x3), "r"(x2));
    asm("cvt.pack.sat.s8.s32.b32 %0, %1, %2, %3;" : "=r"(d) : "r"(x1), "r"(x0), "r"(t));
    return d;
}

// ---------------------------------------------------------------------------
__global__ __launch_bounds__(512, 1)
void contrastive_fused(const float* __restrict__ f, float* __restrict__ out) {
    extern __shared__ char smc[];
    uint32_t sb;
    asm("{ .reg .u64 t; cvta.to.shared.u64 t, %1; cvt.u32.u64 %0, t; }"
        : "=r"(sb) : "l"(smc));
    const int tid = threadIdx.x, lane = tid & 31;
    const int it = blockIdx.x >> 4, jt = blockIdx.x & 15;
    const int i0 = it * 128, j0 = jt * 128;

    // ---- Stage A/B rows as int8 + fused norm quarter-partials --------------
    float* NP = (float*)(smc + S_NP);
#pragma unroll
    for (int r = 0; r < 8; r++) {
        int idx = tid + r * 512;
        int row = idx >> 5;                 // one row per warp per rep
        float4 v = *(const float4*)(f + (size_t)(i0 + row) * 128 + lane * 4);
        *(uint32_t*)(smc + S_A + row * RS + lane * 4) = quant4(v);
        float s = fmaf(v.x, v.x, fmaf(v.y, v.y, fmaf(v.z, v.z, v.w * v.w)));
        s += __shfl_xor_sync(0xffffffffu, s, 8);
        s += __shfl_xor_sync(0xffffffffu, s, 16);
        if (lane < 8) NP[row * 9 + lane] = s;
    }
#pragma unroll
    for (int r = 0; r < 8; r++) {
        int idx = tid + r * 512;
        int row = idx >> 5;
        float4 v = *(const float4*)(f + (size_t)(j0 + row) * 128 + lane * 4);
        *(uint32_t*)(smc + S_B + row * RS + lane * 4) = quant4(v);
        float s = fmaf(v.x, v.x, fmaf(v.y, v.y, fmaf(v.z, v.z, v.w * v.w)));
        s += __shfl_xor_sync(0xffffffffu, s, 8);
        s += __shfl_xor_sync(0xffffffffu, s, 16);
        if (lane < 8) NP[(128 + row) * 9 + lane] = s;
    }
    __syncthreads();

    // ---- Finalize norms (no barrier needed before mainloop) ----------------
    if (tid < 256) {
        const float* p = NP + tid * 9;
        ((float*)(smc + S_NI))[tid] =
            ((p[0] + p[1]) + (p[2] + p[3])) + ((p[4] + p[5]) + (p[6] + p[7]));
    }

    // ---- Mainloop: 32x32 per warp (4x4 warp grid), s8 m16n8k32 -------------
    const int w = tid >> 5;
    const int wm = w >> 2, wn = w & 3;
    const int L7 = lane & 7, Lb3 = (lane >> 3) & 1, Lb4 = (lane >> 4) & 1;

    uint32_t aP0 = sb + S_A + (uint32_t)((wm * 32 + L7 + Lb3 * 8) * RS) + Lb4 * 16;
    uint32_t aP1 = aP0 + 16 * RS;
    uint32_t bP0 = sb + S_B + (uint32_t)((wn * 32 + L7 + Lb4 * 8) * RS) + Lb3 * 16;
    uint32_t bP1 = bP0 + 16 * RS;

    int acc[2][4][4];
#pragma unroll
    for (int mb = 0; mb < 2; mb++)
#pragma unroll
        for (int nb = 0; nb < 4; nb++)
#pragma unroll
            for (int x = 0; x < 4; x++) acc[mb][nb][x] = 0;

#pragma unroll
    for (int s = 0; s < 4; s++) {          // 4 chunks of k=32 int8 (32 B each)
        uint32_t a0[4], a1[4], b0[4], b1[4];
        ldsm4(a0, aP0 + s * 32);
        ldsm4(a1, aP1 + s * 32);
        ldsm4(b0, bP0 + s * 32);
        ldsm4(b1, bP1 + s * 32);
        mma_s8(acc[0][0], a0, b0[0], b0[1]);
        mma_s8(acc[0][1], a0, b0[2], b0[3]);
        mma_s8(acc[0][2], a0, b1[0], b1[1]);
        mma_s8(acc[0][3], a0, b1[2], b1[3]);
        mma_s8(acc[1][0], a1, b0[0], b0[1]);
        mma_s8(acc[1][1], a1, b0[2], b0[3]);
        mma_s8(acc[1][2], a1, b1[0], b1[1]);
        mma_s8(acc[1][3], a1, b1[2], b1[3]);
    }

    // ---- Epilogue: probits + per-row reduction -----------------------------
    const float* NI = (const float*)(smc + S_NI);
    const int g = lane >> 2, tg = lane & 3;
    float* red = (float*)(smc + S_RED);
    __syncthreads();   // orders NI writes + NP reads before RED reuse
#pragma unroll
    for (int mb = 0; mb < 2; mb++) {
        int r0 = wm * 32 + mb * 16 + g;
        int gi0 = i0 + r0, gi1 = gi0 + 8;
        float n0 = 1.f + NI[r0], n1 = 1.f + NI[r0 + 8];
        float s0 = 0.f, s1 = 0.f;
#pragma unroll
        for (int nb = 0; nb < 4; nb++) {
            int cl0 = wn * 32 + nb * 8 + 2 * tg;
            int gj0 = j0 + cl0, gj1 = gj0 + 1;
            float nc0 = NI[128 + cl0], nc1 = NI[128 + cl0 + 1];

            float p00 = frcp(fmaf((float)acc[mb][nb][0], -INV2S2, n0 + nc0));
            float p01 = frcp(fmaf((float)acc[mb][nb][1], -INV2S2, n0 + nc1));
            float p10 = frcp(fmaf((float)acc[mb][nb][2], -INV2S2, n1 + nc0));
            float p11 = frcp(fmaf((float)acc[mb][nb][3], -INV2S2, n1 + nc1));

            if (gj0 == gi0) p00 = 0.f; else if (gj0 == gi0 + BB) g_ppos[gi0] = p00;
            if (gj1 == gi0) p01 = 0.f; else if (gj1 == gi0 + BB) g_ppos[gi0] = p01;
            if (gj0 == gi1) p10 = 0.f; else if (gj0 == gi1 + BB) g_ppos[gi1] = p10;
            if (gj1 == gi1) p11 = 0.f; else if (gj1 == gi1 + BB) g_ppos[gi1] = p11;

            s0 += p00 + p01;
            s1 += p10 + p11;
        }
        s0 += __shfl_xor_sync(0xffffffffu, s0, 1);
        s0 += __shfl_xor_sync(0xffffffffu, s0, 2);
        s1 += __shfl_xor_sync(0xffffffffu, s1, 1);
        s1 += __shfl_xor_sync(0xffffffffu, s1, 2);
        if (tg == 0) {
            red[wn * 128 + r0] = s0;
            red[wn * 128 + r0 + 8] = s1;
        }
    }
    __syncthreads();
    if (tid < 128)
        g_partial[jt * BB + i0 + tid] =
            (red[tid] + red[128 + tid]) + (red[256 + tid] + red[384 + tid]);

    // ---- Last-block finish (deterministic fixed-order sums) ----------------
    __shared__ int sflag;
    if (tid == 0) {
        __threadfence();
        int old = atomicAdd(&g_counter, 1);
        sflag = (old == NBLK - 1);
    }
    __syncthreads();
    if (sflag) {
        __threadfence();
        if (tid == 0) g_counter = 0;       // reset for next graph replay
        float accl = 0.f;
#pragma unroll
        for (int m = 0; m < 2; m++) {
            int i = tid * 2 + m;
            float S = 0.f;
#pragma unroll
            for (int t = 0; t < NJT; t++) S += g_partial[t * BB + i];
            accl += __logf(__fdividef(S, g_ppos[i]));
        }
#pragma unroll
        for (int o = 16; o; o >>= 1) accl += __shfl_xor_sync(0xffffffffu, accl, o);
        float* wsum = (float*)(smc + S_NI);
        if (lane == 0) wsum[tid >> 5] = accl;
        __syncthreads();
        if (tid == 0) {
            float tot = 0.f;
#pragma unroll
            for (int x = 0; x < 16; x++) tot += wsum[x];
            out[0] = tot * (1.0f / (float)BB);
        }
    }
}

// ---------------------------------------------------------------------------
extern "C" void kernel_launch(void* const* d_in, const int* in_sizes, int n_in,
                              void* d_out, int out_size) {
    const float* features = (const float*)d_in[0];
    float* out = (float*)d_out;

    cudaFuncSetAttribute(contrastive_fused,
                         cudaFuncAttributeMaxDynamicSharedMemorySize, S_TOT);
    contrastive_fused<<<NBLK, 512, S_TOT>>>(features, out);
}

// round 11
// speedup vs baseline: 1.9762x; 1.9762x over previous
#include <cuda_runtime.h>
#include <cuda_fp16.h>
#include <cstdint>

#define BB   1024
#define NJT  16
#define NBLK 128              // 8 i-tiles x 16 j-tiles of 128x128, one wave
#define RS   272              // fp16 row: 256 B data + 16 B pad

// byte offsets in dynamic SMEM
#define S_A   0               // 128 rows x 272
#define S_B   34816           // 128 rows x 272
#define S_NI  69632           // 256 floats (norms: [0:128)=A, [128:256)=B)
#define S_NP  70656           // 256 x 9 floats (partials); RED aliases
#define S_RED S_NP            // 4 x 128 floats (NP dead by then)
#define S_TOT 79872

__device__ float g_partial[NJT * BB];
__device__ float g_ppos[BB];
__device__ int   g_counter = 0;

__device__ __forceinline__ float frcp(float x) {
    float r;
    asm("rcp.approx.f32 %0, %1;" : "=f"(r) : "f"(x));
    return r;
}
__device__ __forceinline__ void ldsm4(uint32_t r[4], uint32_t p) {
    asm volatile("ldmatrix.sync.aligned.m8n8.x4.shared.b16 {%0,%1,%2,%3}, [%4];"
                 : "=r"(r[0]), "=r"(r[1]), "=r"(r[2]), "=r"(r[3]) : "r"(p));
}
__device__ __forceinline__ void mma_f16(float c[4], const uint32_t a[4],
                                        uint32_t b0, uint32_t b1) {
    asm volatile(
        "mma.sync.aligned.m16n8k16.row.col.f32.f16.f16.f32 "
        "{%0,%1,%2,%3}, {%4,%5,%6,%7}, {%8,%9}, {%0,%1,%2,%3};"
        : "+f"(c[0]), "+f"(c[1]), "+f"(c[2]), "+f"(c[3])
        : "r"(a[0]), "r"(a[1]), "r"(a[2]), "r"(a[3]), "r"(b0), "r"(b1));
}

// MODE 0: interior tile (no self/pos possible). MODE 1: jt==it (zero diagonal).
// MODE 2: jt==it+8 (capture positive pair).
template<int MODE>
__device__ __forceinline__ void epilogue(char* smc, const float acc[2][4][4],
                                         int wm, int wn, int g, int tg, int i0) {
    const float* NI = (const float*)(smc + S_NI);
    float* red = (float*)(smc + S_RED);
#pragma unroll
    for (int mb = 0; mb < 2; mb++) {
        int r0 = wm * 32 + mb * 16 + g;
        int r1 = r0 + 8;
        float n0 = 1.f + NI[r0], n1 = 1.f + NI[r1];
        float s0 = 0.f, s1 = 0.f;
#pragma unroll
        for (int nb = 0; nb < 4; nb++) {
            int cl0 = wn * 32 + nb * 8 + 2 * tg;
            float nc0 = NI[128 + cl0], nc1 = NI[128 + cl0 + 1];

            float p00 = frcp(n0 + nc0 - 2.f * acc[mb][nb][0]);
            float p01 = frcp(n0 + nc1 - 2.f * acc[mb][nb][1]);
            float p10 = frcp(n1 + nc0 - 2.f * acc[mb][nb][2]);
            float p11 = frcp(n1 + nc1 - 2.f * acc[mb][nb][3]);

            if (MODE == 1) {                     // diagonal tile: zero j==i
                if (cl0 == r0) p00 = 0.f;
                if (cl0 + 1 == r0) p01 = 0.f;
                if (cl0 == r1) p10 = 0.f;
                if (cl0 + 1 == r1) p11 = 0.f;
            }
            if (MODE == 2) {                     // positive tile: j == i + BB
                if (cl0 == r0) g_ppos[i0 + r0] = p00;
                if (cl0 + 1 == r0) g_ppos[i0 + r0] = p01;
                if (cl0 == r1) g_ppos[i0 + r1] = p10;
                if (cl0 + 1 == r1) g_ppos[i0 + r1] = p11;
            }
            s0 += p00 + p01;
            s1 += p10 + p11;
        }
        s0 += __shfl_xor_sync(0xffffffffu, s0, 1);
        s0 += __shfl_xor_sync(0xffffffffu, s0, 2);
        s1 += __shfl_xor_sync(0xffffffffu, s1, 1);
        s1 += __shfl_xor_sync(0xffffffffu, s1, 2);
        if (tg == 0) {
            red[wn * 128 + r0] = s0;
            red[wn * 128 + r1] = s1;
        }
    }
}

// ---------------------------------------------------------------------------
__global__ __launch_bounds__(512, 1)
void contrastive_fused(const float* __restrict__ f, float* __restrict__ out) {
    extern __shared__ char smc[];
    uint32_t sb;
    asm("{ .reg .u64 t; cvta.to.shared.u64 t, %1; cvt.u32.u64 %0, t; }"
        : "=r"(sb) : "l"(smc));
    const int tid = threadIdx.x, lane = tid & 31;
    const int it = blockIdx.x >> 4, jt = blockIdx.x & 15;
    const int i0 = it * 128, j0 = jt * 128;

    // ---- Stage A+B rows as fp16 (merged: 2 LDGs in flight per rep) ---------
    float* NP = (float*)(smc + S_NP);
#pragma unroll
    for (int r = 0; r < 8; r++) {
        int idx = tid + r * 512;
        int row = idx >> 5;                 // one row per warp per rep
        int c4 = (idx & 31) << 2;
        float4 va = *(const float4*)(f + (size_t)(i0 + row) * 128 + c4);
        float4 vb = *(const float4*)(f + (size_t)(j0 + row) * 128 + c4);
        __half2 a0 = __float22half2_rn(make_float2(va.x, va.y));
        __half2 a1 = __float22half2_rn(make_float2(va.z, va.w));
        __half2 b0 = __float22half2_rn(make_float2(vb.x, vb.y));
        __half2 b1 = __float22half2_rn(make_float2(vb.z, vb.w));
        *(uint2*)(smc + S_A + row * RS + c4 * 2) =
            make_uint2(*(uint32_t*)&a0, *(uint32_t*)&a1);
        *(uint2*)(smc + S_B + row * RS + c4 * 2) =
            make_uint2(*(uint32_t*)&b0, *(uint32_t*)&b1);
        float sa = fmaf(va.x, va.x, fmaf(va.y, va.y, fmaf(va.z, va.z, va.w * va.w)));
        float sbn = fmaf(vb.x, vb.x, fmaf(vb.y, vb.y, fmaf(vb.z, vb.z, vb.w * vb.w)));
        sa += __shfl_xor_sync(0xffffffffu, sa, 8);
        sa += __shfl_xor_sync(0xffffffffu, sa, 16);
        sbn += __shfl_xor_sync(0xffffffffu, sbn, 8);
        sbn += __shfl_xor_sync(0xffffffffu, sbn, 16);
        if (lane < 8) {
            NP[row * 9 + lane] = sa;
            NP[(128 + row) * 9 + lane] = sbn;
        }
    }
    __syncthreads();

    // ---- Finalize norms (ordered by the pre-epilogue barrier) --------------
    if (tid < 256) {
        const float* p = NP + tid * 9;
        ((float*)(smc + S_NI))[tid] =
            ((p[0] + p[1]) + (p[2] + p[3])) + ((p[4] + p[5]) + (p[6] + p[7]));
    }

    // ---- Mainloop: 32x32 per warp (4x4 warp grid), fp16 m16n8k16 -----------
    const int w = tid >> 5;
    const int wm = w >> 2, wn = w & 3;
    const int L7 = lane & 7, Lb3 = (lane >> 3) & 1, Lb4 = (lane >> 4) & 1;

    uint32_t aP0 = sb + S_A + (uint32_t)((wm * 32 + L7 + Lb3 * 8) * RS) + Lb4 * 16;
    uint32_t aP1 = aP0 + 16 * RS;
    uint32_t bP0 = sb + S_B + (uint32_t)((wn * 32 + L7 + Lb4 * 8) * RS) + Lb3 * 16;
    uint32_t bP1 = bP0 + 16 * RS;

    float acc[2][4][4];
#pragma unroll
    for (int mb = 0; mb < 2; mb++)
#pragma unroll
        for (int nb = 0; nb < 4; nb++)
#pragma unroll
            for (int x = 0; x < 4; x++) acc[mb][nb][x] = 0.f;

#pragma unroll
    for (int s = 0; s < 8; s++) {
        uint32_t a0[4], a1[4], b0[4], b1[4];
        ldsm4(a0, aP0 + s * 32);
        ldsm4(a1, aP1 + s * 32);
        ldsm4(b0, bP0 + s * 32);
        ldsm4(b1, bP1 + s * 32);
        mma_f16(acc[0][0], a0, b0[0], b0[1]);
        mma_f16(acc[0][1], a0, b0[2], b0[3]);
        mma_f16(acc[0][2], a0, b1[0], b1[1]);
        mma_f16(acc[0][3], a0, b1[2], b1[3]);
        mma_f16(acc[1][0], a1, b0[0], b0[1]);
        mma_f16(acc[1][1], a1, b0[2], b0[3]);
        mma_f16(acc[1][2], a1, b1[0], b1[1]);
        mma_f16(acc[1][3], a1, b1[2], b1[3]);
    }

    // ---- Epilogue (mode specialized per tile; barrier orders NI + RED) -----
    const int g = lane >> 2, tg = lane & 3;
    __syncthreads();
    if (jt == it)          epilogue<1>(smc, acc, wm, wn, g, tg, i0);
    else if (jt == it + 8) epilogue<2>(smc, acc, wm, wn, g, tg, i0);
    else                   epilogue<0>(smc, acc, wm, wn, g, tg, i0);
    __syncthreads();
    {
        const float* red = (const float*)(smc + S_RED);
        if (tid < 128)
            g_partial[jt * BB + i0 + tid] =
                (red[tid] + red[128 + tid]) + (red[256 + tid] + red[384 + tid]);
    }

    // ---- Last-block finish (deterministic fixed-order sums) ----------------
    __shared__ int sflag;
    if (tid == 0) {
        __threadfence();
        int old = atomicAdd(&g_counter, 1);
        sflag = (old == NBLK - 1);
    }
    __syncthreads();
    if (sflag) {
        __threadfence();
        if (tid == 0) g_counter = 0;       // reset for next graph replay
        float accl = 0.f;
#pragma unroll
        for (int m = 0; m < 2; m++) {
            int i = tid * 2 + m;
            float S = 0.f;
#pragma unroll
            for (int t = 0; t < NJT; t++) S += g_partial[t * BB + i];
            accl += __logf(__fdividef(S, g_ppos[i]));
        }
#pragma unroll
        for (int o = 16; o; o >>= 1) accl += __shfl_xor_sync(0xffffffffu, accl, o);
        float* wsum = (float*)(smc + S_NI);
        if (lane == 0) wsum[tid >> 5] = accl;
        __syncthreads();
        if (tid == 0) {
            float tot = 0.f;
#pragma unroll
            for (int x = 0; x < 16; x++) tot += wsum[x];
            out[0] = tot * (1.0f / (float)BB);
        }
    }
}

// ---------------------------------------------------------------------------
extern "C" void kernel_launch(void* const* d_in, const int* in_sizes, int n_in,
                              void* d_out, int out_size) {
    const float* features = (const float*)d_in[0];
    float* out = (float*)d_out;

    cudaFuncSetAttribute(contrastive_fused,
                         cudaFuncAttributeMaxDynamicSharedMemorySize, S_TOT);
    contrastive_fused<<<NBLK, 512, S_TOT>>>(features, out);
}